// round 9
// baseline (speedup 1.0000x reference)
#include <cuda_runtime.h>

// Problem constants (dataset is fixed: 50000 nodes, 800000 edges, 64 feats)
#define MAX_NODES 50048
#define MAX_EDGES 800000
#define SCAN_BLK  1024
#define MAX_SCAN_BLOCKS 64   // ceil(50000/1024) = 49

// Scratch (allocation-free rule: __device__ globals). Zero-init at load;
// g_count / g_ready are re-zeroed by k_gather so graph replays stay correct.
__device__ int g_count[MAX_NODES];
__device__ int g_offset[MAX_NODES + 1];
__device__ int g_cursor[MAX_NODES];
__device__ int g_srow[MAX_EDGES];
__device__ int g_blocksum[MAX_SCAN_BLOCKS];
__device__ int g_ready;                     // published-blocksum counter

// Histogram of destinations. int4-vectorized edge reads (E % 4 == 0).
__global__ void k_hist(const int* __restrict__ col, int E4) {
    int i = blockIdx.x * blockDim.x + threadIdx.x;
    if (i < E4) {
        int4 c = reinterpret_cast<const int4*>(col)[i];
        atomicAdd(&g_count[c.x], 1);
        atomicAdd(&g_count[c.y], 1);
        atomicAdd(&g_count[c.z], 1);
        atomicAdd(&g_count[c.w], 1);
    }
}

// Single-pass scan: 49 co-resident blocks. Each block scans its tile,
// publishes the tile total, spins for all totals, adds its base.
__global__ void k_scan(int n, int nblocks) {
    __shared__ int s_warp[32];
    __shared__ int s_wpre[32];
    __shared__ int s_sums[MAX_SCAN_BLOCKS];
    int t = threadIdx.x;
    int wid = t >> 5, lane = t & 31;
    int b = blockIdx.x;
    int i = b * SCAN_BLK + t;
    int v = (i < n) ? g_count[i] : 0;

    int incl = v;
    #pragma unroll
    for (int o = 1; o < 32; o <<= 1) {
        int u = __shfl_up_sync(0xffffffffu, incl, o);
        if (lane >= o) incl += u;
    }
    if (lane == 31) s_warp[wid] = incl;
    __syncthreads();

    if (wid == 0) {
        int w = s_warp[lane];
        int winc = w;
        #pragma unroll
        for (int o = 1; o < 32; o <<= 1) {
            int u = __shfl_up_sync(0xffffffffu, winc, o);
            if (lane >= o) winc += u;
        }
        s_wpre[lane] = winc - w;
        if (lane == 31) {
            g_blocksum[b] = winc;
            __threadfence();
            atomicAdd(&g_ready, 1);
        }
    }
    __syncthreads();

    if (t == 0) {
        while (atomicAdd(&g_ready, 0) < nblocks) { __nanosleep(64); }
    }
    __syncthreads();
    if (t < MAX_SCAN_BLOCKS) s_sums[t] = (t < nblocks) ? __ldcg(&g_blocksum[t]) : 0;
    __syncthreads();

    int base = 0;
    for (int j = 0; j < b; j++) base += s_sums[j];

    int excl = base + s_wpre[wid] + incl - v;
    if (i < n) {
        g_offset[i] = excl;
        g_cursor[i] = excl;
        if (i == n - 1) g_offset[n] = excl + v;      // total == E
    }
}

// Counting sort of edge sources by destination. 8 edges/thread for MLP.
__global__ void k_scatter(const int* __restrict__ row, const int* __restrict__ col, int E4) {
    int i = (blockIdx.x * blockDim.x + threadIdx.x) * 2;
    if (i + 1 < E4) {
        int4 r0 = reinterpret_cast<const int4*>(row)[i];
        int4 r1 = reinterpret_cast<const int4*>(row)[i + 1];
        int4 c0 = reinterpret_cast<const int4*>(col)[i];
        int4 c1 = reinterpret_cast<const int4*>(col)[i + 1];
        g_srow[atomicAdd(&g_cursor[c0.x], 1)] = r0.x;
        g_srow[atomicAdd(&g_cursor[c0.y], 1)] = r0.y;
        g_srow[atomicAdd(&g_cursor[c0.z], 1)] = r0.z;
        g_srow[atomicAdd(&g_cursor[c0.w], 1)] = r0.w;
        g_srow[atomicAdd(&g_cursor[c1.x], 1)] = r1.x;
        g_srow[atomicAdd(&g_cursor[c1.y], 1)] = r1.y;
        g_srow[atomicAdd(&g_cursor[c1.z], 1)] = r1.z;
        g_srow[atomicAdd(&g_cursor[c1.w], 1)] = r1.w;
    } else if (i < E4) {
        int4 r0 = reinterpret_cast<const int4*>(row)[i];
        int4 c0 = reinterpret_cast<const int4*>(col)[i];
        g_srow[atomicAdd(&g_cursor[c0.x], 1)] = r0.x;
        g_srow[atomicAdd(&g_cursor[c0.y], 1)] = r0.y;
        g_srow[atomicAdd(&g_cursor[c0.z], 1)] = r0.z;
        g_srow[atomicAdd(&g_cursor[c0.w], 1)] = r0.w;
    }
}

// ONE WARP per destination node. Lanes 0-15 handle edge i, lanes 16-31 edge
// i+1; each lane accumulates a float4 feature slice. Uniform loop bounds ->
// zero divergence; 4-step unroll = 8 edges in flight per warp. Epilogue
// combines the two half-warp accumulators with shfl_xor(16).
// Also resets g_count / g_ready for the next graph replay.
__global__ void k_gather(const float* __restrict__ x, float* __restrict__ out, int n) {
    int gtid = blockIdx.x * blockDim.x + threadIdx.x;

    if (gtid < MAX_NODES / 4)
        reinterpret_cast<int4*>(g_count)[gtid] = make_int4(0, 0, 0, 0);
    if (gtid == 0) g_ready = 0;

    int node = gtid >> 5;              // one warp per node
    int lane = threadIdx.x & 31;
    if (node >= n) return;
    int half = lane >> 4;              // which of the 2 concurrent edges
    int hw   = lane & 15;              // feature slice within edge
    int start = g_offset[node];
    int end   = g_offset[node + 1];

    float4 a0 = make_float4(0.f, 0.f, 0.f, 0.f);
    float4 a1 = make_float4(0.f, 0.f, 0.f, 0.f);
    float4 a2 = make_float4(0.f, 0.f, 0.f, 0.f);
    float4 a3 = make_float4(0.f, 0.f, 0.f, 0.f);

    int i = start;
    for (; i + 8 <= end; i += 8) {
        int r0 = g_srow[i     + half];
        int r1 = g_srow[i + 2 + half];
        int r2 = g_srow[i + 4 + half];
        int r3 = g_srow[i + 6 + half];
        float4 v0 = reinterpret_cast<const float4*>(x + ((size_t)r0 << 6))[hw];
        float4 v1 = reinterpret_cast<const float4*>(x + ((size_t)r1 << 6))[hw];
        float4 v2 = reinterpret_cast<const float4*>(x + ((size_t)r2 << 6))[hw];
        float4 v3 = reinterpret_cast<const float4*>(x + ((size_t)r3 << 6))[hw];
        a0.x += v0.x; a0.y += v0.y; a0.z += v0.z; a0.w += v0.w;
        a1.x += v1.x; a1.y += v1.y; a1.z += v1.z; a1.w += v1.w;
        a2.x += v2.x; a2.y += v2.y; a2.z += v2.z; a2.w += v2.w;
        a3.x += v3.x; a3.y += v3.y; a3.z += v3.z; a3.w += v3.w;
    }
    for (; i + 2 <= end; i += 2) {
        int r0 = g_srow[i + half];
        float4 v0 = reinterpret_cast<const float4*>(x + ((size_t)r0 << 6))[hw];
        a0.x += v0.x; a0.y += v0.y; a0.z += v0.z; a0.w += v0.w;
    }
    if (i < end && half == 0) {        // odd final edge: half 0 only
        int r0 = g_srow[i];
        float4 v0 = reinterpret_cast<const float4*>(x + ((size_t)r0 << 6))[hw];
        a0.x += v0.x; a0.y += v0.y; a0.z += v0.z; a0.w += v0.w;
    }

    // combine 4 accumulators, then the two half-warps (same hw = same feats)
    float4 a;
    a.x = a0.x + a1.x + a2.x + a3.x;
    a.y = a0.y + a1.y + a2.y + a3.y;
    a.z = a0.z + a1.z + a2.z + a3.z;
    a.w = a0.w + a1.w + a2.w + a3.w;
    a.x += __shfl_xor_sync(0xffffffffu, a.x, 16);
    a.y += __shfl_xor_sync(0xffffffffu, a.y, 16);
    a.z += __shfl_xor_sync(0xffffffffu, a.z, 16);
    a.w += __shfl_xor_sync(0xffffffffu, a.w, 16);

    int deg = end - start;
    float inv = 1.0f / (float)(deg > 0 ? deg : 1);
    if (half == 0) {
        float4 o = make_float4(a.x * inv, a.y * inv, a.z * inv, a.w * inv);
        *reinterpret_cast<float4*>(out + ((size_t)node << 6) + (hw << 2)) = o;
    }
}

extern "C" void kernel_launch(void* const* d_in, const int* in_sizes, int n_in,
                              void* d_out, int out_size) {
    const float* x    = (const float*)d_in[0];
    const int*   edge = (const int*)d_in[1];
    float*       out  = (float*)d_out;

    const int n  = in_sizes[0] / 64;    // 50000
    const int E  = in_sizes[1] / 2;     // 800000
    const int E4 = E / 4;               // 200000 (E % 4 == 0)
    const int* row = edge;              // edge_index[0, :]
    const int* col = edge + E;          // edge_index[1, :]

    const int nb_scan    = (n + SCAN_BLK - 1) / SCAN_BLK;   // 49
    const int scatBlocks = (E4 / 2 + 255) / 256;            // 391

    k_hist   <<<(E4 + 255) / 256, 256>>>(col, E4);
    k_scan   <<<nb_scan, SCAN_BLK>>>(n, nb_scan);
    k_scatter<<<scatBlocks, 256>>>(row, col, E4);
    // one warp per node: 8 warps / 256-thread block
    k_gather <<<(n + 7) / 8, 256>>>(x, out, n);
}

// round 11
// speedup vs baseline: 1.0756x; 1.0756x over previous
#include <cuda_runtime.h>

// Problem constants (dataset is fixed: 50000 nodes, 800000 edges, 64 feats)
#define MAX_NODES 50048
#define MAX_EDGES 800000
#define SCAN_BLK  1024
#define MAX_SCAN_BLOCKS 64   // ceil(50000/1024) = 49

// Scratch (allocation-free rule: __device__ globals). Zero-init at load;
// g_count / g_ready are re-zeroed by k_gather so graph replays stay correct.
__device__ int g_count[MAX_NODES];
__device__ int g_offset[MAX_NODES + 1];
__device__ int g_cursor[MAX_NODES];
__device__ int g_srow[MAX_EDGES];
__device__ int g_blocksum[MAX_SCAN_BLOCKS];
__device__ int g_ready;                     // published-blocksum counter

// Histogram of destinations. int4-vectorized edge reads (E % 4 == 0).
__global__ void k_hist(const int* __restrict__ col, int E4) {
    int i = blockIdx.x * blockDim.x + threadIdx.x;
    if (i < E4) {
        int4 c = reinterpret_cast<const int4*>(col)[i];
        atomicAdd(&g_count[c.x], 1);
        atomicAdd(&g_count[c.y], 1);
        atomicAdd(&g_count[c.z], 1);
        atomicAdd(&g_count[c.w], 1);
    }
}

// Single-pass scan: 49 co-resident blocks. Each block scans its tile,
// publishes the tile total, spins for all totals, adds its base.
__global__ void k_scan(int n, int nblocks) {
    __shared__ int s_warp[32];
    __shared__ int s_wpre[32];
    __shared__ int s_sums[MAX_SCAN_BLOCKS];
    int t = threadIdx.x;
    int wid = t >> 5, lane = t & 31;
    int b = blockIdx.x;
    int i = b * SCAN_BLK + t;
    int v = (i < n) ? g_count[i] : 0;

    int incl = v;
    #pragma unroll
    for (int o = 1; o < 32; o <<= 1) {
        int u = __shfl_up_sync(0xffffffffu, incl, o);
        if (lane >= o) incl += u;
    }
    if (lane == 31) s_warp[wid] = incl;
    __syncthreads();

    if (wid == 0) {
        int w = s_warp[lane];
        int winc = w;
        #pragma unroll
        for (int o = 1; o < 32; o <<= 1) {
            int u = __shfl_up_sync(0xffffffffu, winc, o);
            if (lane >= o) winc += u;
        }
        s_wpre[lane] = winc - w;
        if (lane == 31) {
            g_blocksum[b] = winc;
            __threadfence();
            atomicAdd(&g_ready, 1);
        }
    }
    __syncthreads();

    if (t == 0) {
        while (atomicAdd(&g_ready, 0) < nblocks) { __nanosleep(64); }
    }
    __syncthreads();
    if (t < MAX_SCAN_BLOCKS) s_sums[t] = (t < nblocks) ? __ldcg(&g_blocksum[t]) : 0;
    __syncthreads();

    int base = 0;
    for (int j = 0; j < b; j++) base += s_sums[j];

    int excl = base + s_wpre[wid] + incl - v;
    if (i < n) {
        g_offset[i] = excl;
        g_cursor[i] = excl;
        if (i == n - 1) g_offset[n] = excl + v;      // total == E
    }
}

// Counting sort of edge sources by destination. 8 edges/thread for MLP.
__global__ void k_scatter(const int* __restrict__ row, const int* __restrict__ col, int E4) {
    int i = (blockIdx.x * blockDim.x + threadIdx.x) * 2;
    if (i + 1 < E4) {
        int4 r0 = reinterpret_cast<const int4*>(row)[i];
        int4 r1 = reinterpret_cast<const int4*>(row)[i + 1];
        int4 c0 = reinterpret_cast<const int4*>(col)[i];
        int4 c1 = reinterpret_cast<const int4*>(col)[i + 1];
        g_srow[atomicAdd(&g_cursor[c0.x], 1)] = r0.x;
        g_srow[atomicAdd(&g_cursor[c0.y], 1)] = r0.y;
        g_srow[atomicAdd(&g_cursor[c0.z], 1)] = r0.z;
        g_srow[atomicAdd(&g_cursor[c0.w], 1)] = r0.w;
        g_srow[atomicAdd(&g_cursor[c1.x], 1)] = r1.x;
        g_srow[atomicAdd(&g_cursor[c1.y], 1)] = r1.y;
        g_srow[atomicAdd(&g_cursor[c1.z], 1)] = r1.z;
        g_srow[atomicAdd(&g_cursor[c1.w], 1)] = r1.w;
    } else if (i < E4) {
        int4 r0 = reinterpret_cast<const int4*>(row)[i];
        int4 c0 = reinterpret_cast<const int4*>(col)[i];
        g_srow[atomicAdd(&g_cursor[c0.x], 1)] = r0.x;
        g_srow[atomicAdd(&g_cursor[c0.y], 1)] = r0.y;
        g_srow[atomicAdd(&g_cursor[c0.z], 1)] = r0.z;
        g_srow[atomicAdd(&g_cursor[c0.w], 1)] = r0.w;
    }
}

// HALF-WARP per destination node; lane handles feats [4*hw, 4*hw+3] as float4.
// Software-pipelined: next batch of 4 indices is loaded while current batch's
// data loads are in flight, halving the dependent-chain latency per batch.
// Also resets g_count / g_ready for the next graph replay.
__global__ void k_gather(const float* __restrict__ x, float* __restrict__ out, int n) {
    int gtid = blockIdx.x * blockDim.x + threadIdx.x;

    if (gtid < MAX_NODES / 4)
        reinterpret_cast<int4*>(g_count)[gtid] = make_int4(0, 0, 0, 0);
    if (gtid == 0) g_ready = 0;

    int node = gtid >> 4;              // half-warp group id
    int hw   = threadIdx.x & 15;       // feature slice within edge
    if (node >= n) return;
    int start = g_offset[node];
    int end   = g_offset[node + 1];

    float4 a0 = make_float4(0.f, 0.f, 0.f, 0.f);
    float4 a1 = make_float4(0.f, 0.f, 0.f, 0.f);
    float4 a2 = make_float4(0.f, 0.f, 0.f, 0.f);
    float4 a3 = make_float4(0.f, 0.f, 0.f, 0.f);

    int i = start;
    if (i + 4 <= end) {
        // prologue: first index batch
        int j0 = g_srow[i];
        int j1 = g_srow[i + 1];
        int j2 = g_srow[i + 2];
        int j3 = g_srow[i + 3];
        for (; i + 8 <= end; i += 4) {
            // data loads for current batch (go out first)
            float4 v0 = reinterpret_cast<const float4*>(x + ((size_t)j0 << 6))[hw];
            float4 v1 = reinterpret_cast<const float4*>(x + ((size_t)j1 << 6))[hw];
            float4 v2 = reinterpret_cast<const float4*>(x + ((size_t)j2 << 6))[hw];
            float4 v3 = reinterpret_cast<const float4*>(x + ((size_t)j3 << 6))[hw];
            // prefetch next index batch (independent of v*)
            int t0 = g_srow[i + 4];
            int t1 = g_srow[i + 5];
            int t2 = g_srow[i + 6];
            int t3 = g_srow[i + 7];
            a0.x += v0.x; a0.y += v0.y; a0.z += v0.z; a0.w += v0.w;
            a1.x += v1.x; a1.y += v1.y; a1.z += v1.z; a1.w += v1.w;
            a2.x += v2.x; a2.y += v2.y; a2.z += v2.z; a2.w += v2.w;
            a3.x += v3.x; a3.y += v3.y; a3.z += v3.z; a3.w += v3.w;
            j0 = t0; j1 = t1; j2 = t2; j3 = t3;
        }
        // epilogue: last prefetched batch
        {
            float4 v0 = reinterpret_cast<const float4*>(x + ((size_t)j0 << 6))[hw];
            float4 v1 = reinterpret_cast<const float4*>(x + ((size_t)j1 << 6))[hw];
            float4 v2 = reinterpret_cast<const float4*>(x + ((size_t)j2 << 6))[hw];
            float4 v3 = reinterpret_cast<const float4*>(x + ((size_t)j3 << 6))[hw];
            a0.x += v0.x; a0.y += v0.y; a0.z += v0.z; a0.w += v0.w;
            a1.x += v1.x; a1.y += v1.y; a1.z += v1.z; a1.w += v1.w;
            a2.x += v2.x; a2.y += v2.y; a2.z += v2.z; a2.w += v2.w;
            a3.x += v3.x; a3.y += v3.y; a3.z += v3.z; a3.w += v3.w;
            i += 4;
        }
    }
    for (; i < end; i++) {
        int r0 = g_srow[i];
        float4 v0 = reinterpret_cast<const float4*>(x + ((size_t)r0 << 6))[hw];
        a0.x += v0.x; a0.y += v0.y; a0.z += v0.z; a0.w += v0.w;
    }

    int deg = end - start;
    float inv = 1.0f / (float)(deg > 0 ? deg : 1);
    float4 o;
    o.x = (a0.x + a1.x + a2.x + a3.x) * inv;
    o.y = (a0.y + a1.y + a2.y + a3.y) * inv;
    o.z = (a0.z + a1.z + a2.z + a3.z) * inv;
    o.w = (a0.w + a1.w + a2.w + a3.w) * inv;
    *reinterpret_cast<float4*>(out + ((size_t)node << 6) + (hw << 2)) = o;
}

extern "C" void kernel_launch(void* const* d_in, const int* in_sizes, int n_in,
                              void* d_out, int out_size) {
    const float* x    = (const float*)d_in[0];
    const int*   edge = (const int*)d_in[1];
    float*       out  = (float*)d_out;

    const int n  = in_sizes[0] / 64;    // 50000
    const int E  = in_sizes[1] / 2;     // 800000
    const int E4 = E / 4;               // 200000 (E % 4 == 0)
    const int* row = edge;              // edge_index[0, :]
    const int* col = edge + E;          // edge_index[1, :]

    const int nb_scan    = (n + SCAN_BLK - 1) / SCAN_BLK;   // 49
    const int scatBlocks = (E4 / 2 + 255) / 256;            // 391

    k_hist   <<<(E4 + 255) / 256, 256>>>(col, E4);
    k_scan   <<<nb_scan, SCAN_BLK>>>(n, nb_scan);
    k_scatter<<<scatBlocks, 256>>>(row, col, E4);
    // half-warp per node: 16 groups / 256-thread block
    k_gather <<<(n + 15) / 16, 256>>>(x, out, n);
}

// round 12
// speedup vs baseline: 1.1194x; 1.0407x over previous
#include <cuda_runtime.h>

// Problem constants (dataset is fixed: 50000 nodes, 800000 edges, 64 feats)
#define MAX_NODES 50048
#define MAX_EDGES 800000
#define SCAN_BLK  1024
#define MAX_SCAN_BLOCKS 64   // ceil(50000/1024) = 49

// Scratch (allocation-free rule: __device__ globals). Zero-init at load;
// g_count / g_ready are re-zeroed by k_gather so graph replays stay correct.
__device__ int g_count[MAX_NODES];
__device__ int g_offset[MAX_NODES + 1];
__device__ int g_rank[MAX_EDGES];           // per-edge rank within its bucket
__device__ int g_srow[MAX_EDGES];
__device__ int g_blocksum[MAX_SCAN_BLOCKS];
__device__ int g_ready;                     // published-blocksum counter

// Histogram of destinations; the atomic's return value is the edge's rank
// within its destination bucket -> stored for the atomic-free scatter.
__global__ void k_hist(const int* __restrict__ col, int E4) {
    int i = blockIdx.x * blockDim.x + threadIdx.x;
    if (i < E4) {
        int4 c = reinterpret_cast<const int4*>(col)[i];
        int4 rk;
        rk.x = atomicAdd(&g_count[c.x], 1);
        rk.y = atomicAdd(&g_count[c.y], 1);
        rk.z = atomicAdd(&g_count[c.z], 1);
        rk.w = atomicAdd(&g_count[c.w], 1);
        reinterpret_cast<int4*>(g_rank)[i] = rk;
    }
}

// Single-pass scan: 49 co-resident blocks. Each block scans its tile,
// publishes the tile total, spins for all totals, adds its base.
__global__ void k_scan(int n, int nblocks) {
    __shared__ int s_warp[32];
    __shared__ int s_wpre[32];
    __shared__ int s_sums[MAX_SCAN_BLOCKS];
    int t = threadIdx.x;
    int wid = t >> 5, lane = t & 31;
    int b = blockIdx.x;
    int i = b * SCAN_BLK + t;
    int v = (i < n) ? g_count[i] : 0;

    int incl = v;
    #pragma unroll
    for (int o = 1; o < 32; o <<= 1) {
        int u = __shfl_up_sync(0xffffffffu, incl, o);
        if (lane >= o) incl += u;
    }
    if (lane == 31) s_warp[wid] = incl;
    __syncthreads();

    if (wid == 0) {
        int w = s_warp[lane];
        int winc = w;
        #pragma unroll
        for (int o = 1; o < 32; o <<= 1) {
            int u = __shfl_up_sync(0xffffffffu, winc, o);
            if (lane >= o) winc += u;
        }
        s_wpre[lane] = winc - w;
        if (lane == 31) {
            g_blocksum[b] = winc;
            __threadfence();
            atomicAdd(&g_ready, 1);
        }
    }
    __syncthreads();

    if (t == 0) {
        while (atomicAdd(&g_ready, 0) < nblocks) { __nanosleep(64); }
    }
    __syncthreads();
    if (t < MAX_SCAN_BLOCKS) s_sums[t] = (t < nblocks) ? __ldcg(&g_blocksum[t]) : 0;
    __syncthreads();

    int base = 0;
    for (int j = 0; j < b; j++) base += s_sums[j];

    int excl = base + s_wpre[wid] + incl - v;
    if (i < n) {
        g_offset[i] = excl;
        if (i == n - 1) g_offset[n] = excl + v;      // total == E
    }
}

// ATOMIC-FREE counting-sort scatter: position = offset[col] + rank[edge].
// Three coalesced int4 loads + 4 independent L2 offset gathers + 4 stores.
__global__ void k_scatter(const int* __restrict__ row, const int* __restrict__ col, int E4) {
    int i = blockIdx.x * blockDim.x + threadIdx.x;
    if (i < E4) {
        int4 r  = reinterpret_cast<const int4*>(row)[i];
        int4 c  = reinterpret_cast<const int4*>(col)[i];
        int4 rk = reinterpret_cast<const int4*>(g_rank)[i];
        int o0 = g_offset[c.x];
        int o1 = g_offset[c.y];
        int o2 = g_offset[c.z];
        int o3 = g_offset[c.w];
        g_srow[o0 + rk.x] = r.x;
        g_srow[o1 + rk.y] = r.y;
        g_srow[o2 + rk.z] = r.z;
        g_srow[o3 + rk.w] = r.w;
    }
}

// HALF-WARP per destination node; lane handles feats [4*hw, 4*hw+3] as float4.
// 4-deep independent accumulators. Also resets g_count / g_ready for replay.
__global__ void k_gather(const float* __restrict__ x, float* __restrict__ out, int n) {
    int gtid = blockIdx.x * blockDim.x + threadIdx.x;

    if (gtid < MAX_NODES / 4)
        reinterpret_cast<int4*>(g_count)[gtid] = make_int4(0, 0, 0, 0);
    if (gtid == 0) g_ready = 0;

    int node = gtid >> 4;              // half-warp group id
    int hw   = threadIdx.x & 15;       // feature slice within edge
    if (node >= n) return;
    int start = g_offset[node];
    int end   = g_offset[node + 1];

    float4 a0 = make_float4(0.f, 0.f, 0.f, 0.f);
    float4 a1 = make_float4(0.f, 0.f, 0.f, 0.f);
    float4 a2 = make_float4(0.f, 0.f, 0.f, 0.f);
    float4 a3 = make_float4(0.f, 0.f, 0.f, 0.f);

    int i = start;
    for (; i + 4 <= end; i += 4) {
        int r0 = g_srow[i];
        int r1 = g_srow[i + 1];
        int r2 = g_srow[i + 2];
        int r3 = g_srow[i + 3];
        float4 v0 = reinterpret_cast<const float4*>(x + ((size_t)r0 << 6))[hw];
        float4 v1 = reinterpret_cast<const float4*>(x + ((size_t)r1 << 6))[hw];
        float4 v2 = reinterpret_cast<const float4*>(x + ((size_t)r2 << 6))[hw];
        float4 v3 = reinterpret_cast<const float4*>(x + ((size_t)r3 << 6))[hw];
        a0.x += v0.x; a0.y += v0.y; a0.z += v0.z; a0.w += v0.w;
        a1.x += v1.x; a1.y += v1.y; a1.z += v1.z; a1.w += v1.w;
        a2.x += v2.x; a2.y += v2.y; a2.z += v2.z; a2.w += v2.w;
        a3.x += v3.x; a3.y += v3.y; a3.z += v3.z; a3.w += v3.w;
    }
    for (; i < end; i++) {
        int r0 = g_srow[i];
        float4 v0 = reinterpret_cast<const float4*>(x + ((size_t)r0 << 6))[hw];
        a0.x += v0.x; a0.y += v0.y; a0.z += v0.z; a0.w += v0.w;
    }

    int deg = end - start;
    float inv = 1.0f / (float)(deg > 0 ? deg : 1);
    float4 o;
    o.x = (a0.x + a1.x + a2.x + a3.x) * inv;
    o.y = (a0.y + a1.y + a2.y + a3.y) * inv;
    o.z = (a0.z + a1.z + a2.z + a3.z) * inv;
    o.w = (a0.w + a1.w + a2.w + a3.w) * inv;
    *reinterpret_cast<float4*>(out + ((size_t)node << 6) + (hw << 2)) = o;
}

extern "C" void kernel_launch(void* const* d_in, const int* in_sizes, int n_in,
                              void* d_out, int out_size) {
    const float* x    = (const float*)d_in[0];
    const int*   edge = (const int*)d_in[1];
    float*       out  = (float*)d_out;

    const int n  = in_sizes[0] / 64;    // 50000
    const int E  = in_sizes[1] / 2;     // 800000
    const int E4 = E / 4;               // 200000 (E % 4 == 0)
    const int* row = edge;              // edge_index[0, :]
    const int* col = edge + E;          // edge_index[1, :]

    const int nb_scan = (n + SCAN_BLK - 1) / SCAN_BLK;   // 49

    k_hist   <<<(E4 + 255) / 256, 256>>>(col, E4);
    k_scan   <<<nb_scan, SCAN_BLK>>>(n, nb_scan);
    k_scatter<<<(E4 + 255) / 256, 256>>>(row, col, E4);
    // half-warp per node: 16 groups / 256-thread block
    k_gather <<<(n + 15) / 16, 256>>>(x, out, n);
}

// round 13
// speedup vs baseline: 1.1305x; 1.0099x over previous
#include <cuda_runtime.h>
#include <cuda_fp16.h>

// Problem constants (dataset is fixed: 50000 nodes, 800000 edges, 64 feats)
#define MAX_NODES 50048
#define MAX_EDGES 800000
#define SCAN_BLK  1024
#define MAX_SCAN_BLOCKS 64   // ceil(50000/1024) = 49
#define N_FIXED   50000

// Scratch (allocation-free rule: __device__ globals). Zero-init at load;
// g_count / g_ready are re-zeroed by k_gather so graph replays stay correct.
__device__ int    g_count[MAX_NODES];
__device__ int    g_offset[MAX_NODES + 1];
__device__ int    g_rank[MAX_EDGES];        // per-edge rank within its bucket
__device__ int    g_srow[MAX_EDGES];
__device__ int    g_blocksum[MAX_SCAN_BLOCKS];
__device__ int    g_ready;                  // published-blocksum counter
__device__ __half g_xh[N_FIXED * 64];       // fp16 staging copy of x (6.4 MB)

// Fused: blocks [0, cvtBlocks) convert x->fp16; the rest histogram the
// destinations AND record each edge's bucket rank (atomic return value).
// The convert blocks' pure bandwidth hides the hist blocks' atomic latency.
__global__ void k_prep(const float* __restrict__ x, const int* __restrict__ col,
                       int n16, int E4, int cvtBlocks) {
    if (blockIdx.x < cvtBlocks) {
        int i = blockIdx.x * blockDim.x + threadIdx.x;
        if (i < n16) {
            float4 v = reinterpret_cast<const float4*>(x)[i];
            __half2 h0 = __floats2half2_rn(v.x, v.y);
            __half2 h1 = __floats2half2_rn(v.z, v.w);
            uint2 u;
            u.x = *reinterpret_cast<unsigned*>(&h0);
            u.y = *reinterpret_cast<unsigned*>(&h1);
            reinterpret_cast<uint2*>(g_xh)[i] = u;
        }
    } else {
        int i = (blockIdx.x - cvtBlocks) * blockDim.x + threadIdx.x;
        if (i < E4) {
            int4 c = reinterpret_cast<const int4*>(col)[i];
            int4 rk;
            rk.x = atomicAdd(&g_count[c.x], 1);
            rk.y = atomicAdd(&g_count[c.y], 1);
            rk.z = atomicAdd(&g_count[c.z], 1);
            rk.w = atomicAdd(&g_count[c.w], 1);
            reinterpret_cast<int4*>(g_rank)[i] = rk;
        }
    }
}

// Single-pass scan: 49 co-resident blocks. Each block scans its tile,
// publishes the tile total, spins for all totals, adds its base.
__global__ void k_scan(int n, int nblocks) {
    __shared__ int s_warp[32];
    __shared__ int s_wpre[32];
    __shared__ int s_sums[MAX_SCAN_BLOCKS];
    int t = threadIdx.x;
    int wid = t >> 5, lane = t & 31;
    int b = blockIdx.x;
    int i = b * SCAN_BLK + t;
    int v = (i < n) ? g_count[i] : 0;

    int incl = v;
    #pragma unroll
    for (int o = 1; o < 32; o <<= 1) {
        int u = __shfl_up_sync(0xffffffffu, incl, o);
        if (lane >= o) incl += u;
    }
    if (lane == 31) s_warp[wid] = incl;
    __syncthreads();

    if (wid == 0) {
        int w = s_warp[lane];
        int winc = w;
        #pragma unroll
        for (int o = 1; o < 32; o <<= 1) {
            int u = __shfl_up_sync(0xffffffffu, winc, o);
            if (lane >= o) winc += u;
        }
        s_wpre[lane] = winc - w;
        if (lane == 31) {
            g_blocksum[b] = winc;
            __threadfence();
            atomicAdd(&g_ready, 1);
        }
    }
    __syncthreads();

    if (t == 0) {
        while (atomicAdd(&g_ready, 0) < nblocks) { __nanosleep(64); }
    }
    __syncthreads();
    if (t < MAX_SCAN_BLOCKS) s_sums[t] = (t < nblocks) ? __ldcg(&g_blocksum[t]) : 0;
    __syncthreads();

    int base = 0;
    for (int j = 0; j < b; j++) base += s_sums[j];

    int excl = base + s_wpre[wid] + incl - v;
    if (i < n) {
        g_offset[i] = excl;
        if (i == n - 1) g_offset[n] = excl + v;      // total == E
    }
}

// ATOMIC-FREE counting-sort scatter: position = offset[col] + rank[edge].
__global__ void k_scatter(const int* __restrict__ row, const int* __restrict__ col, int E4) {
    int i = blockIdx.x * blockDim.x + threadIdx.x;
    if (i < E4) {
        int4 r  = reinterpret_cast<const int4*>(row)[i];
        int4 c  = reinterpret_cast<const int4*>(col)[i];
        int4 rk = reinterpret_cast<const int4*>(g_rank)[i];
        int o0 = g_offset[c.x];
        int o1 = g_offset[c.y];
        int o2 = g_offset[c.z];
        int o3 = g_offset[c.w];
        g_srow[o0 + rk.x] = r.x;
        g_srow[o1 + rk.y] = r.y;
        g_srow[o2 + rk.z] = r.z;
        g_srow[o3 + rk.w] = r.w;
    }
}

// HALF-WARP per destination node; lane handles feats [4*hw, 4*hw+3].
// One edge = 16 lanes x 8B fp16 = one 128B line. fp32 accumulation.
// Also resets g_count / g_ready for the next graph replay.
__global__ void k_gather(float* __restrict__ out, int n) {
    int gtid = blockIdx.x * blockDim.x + threadIdx.x;

    if (gtid < MAX_NODES / 4)
        reinterpret_cast<int4*>(g_count)[gtid] = make_int4(0, 0, 0, 0);
    if (gtid == 0) g_ready = 0;

    int node = gtid >> 4;              // half-warp group id
    int hw   = threadIdx.x & 15;       // feature slice within edge
    if (node >= n) return;
    int start = g_offset[node];
    int end   = g_offset[node + 1];

    float4 a0 = make_float4(0.f, 0.f, 0.f, 0.f);
    float4 a1 = make_float4(0.f, 0.f, 0.f, 0.f);
    float4 a2 = make_float4(0.f, 0.f, 0.f, 0.f);
    float4 a3 = make_float4(0.f, 0.f, 0.f, 0.f);

    int i = start;
    for (; i + 4 <= end; i += 4) {
        int r0 = g_srow[i];
        int r1 = g_srow[i + 1];
        int r2 = g_srow[i + 2];
        int r3 = g_srow[i + 3];
        uint2 u0 = reinterpret_cast<const uint2*>(g_xh + ((size_t)r0 << 6))[hw];
        uint2 u1 = reinterpret_cast<const uint2*>(g_xh + ((size_t)r1 << 6))[hw];
        uint2 u2 = reinterpret_cast<const uint2*>(g_xh + ((size_t)r2 << 6))[hw];
        uint2 u3 = reinterpret_cast<const uint2*>(g_xh + ((size_t)r3 << 6))[hw];
        {
            float2 lo = __half22float2(*reinterpret_cast<__half2*>(&u0.x));
            float2 hi = __half22float2(*reinterpret_cast<__half2*>(&u0.y));
            a0.x += lo.x; a0.y += lo.y; a0.z += hi.x; a0.w += hi.y;
        }
        {
            float2 lo = __half22float2(*reinterpret_cast<__half2*>(&u1.x));
            float2 hi = __half22float2(*reinterpret_cast<__half2*>(&u1.y));
            a1.x += lo.x; a1.y += lo.y; a1.z += hi.x; a1.w += hi.y;
        }
        {
            float2 lo = __half22float2(*reinterpret_cast<__half2*>(&u2.x));
            float2 hi = __half22float2(*reinterpret_cast<__half2*>(&u2.y));
            a2.x += lo.x; a2.y += lo.y; a2.z += hi.x; a2.w += hi.y;
        }
        {
            float2 lo = __half22float2(*reinterpret_cast<__half2*>(&u3.x));
            float2 hi = __half22float2(*reinterpret_cast<__half2*>(&u3.y));
            a3.x += lo.x; a3.y += lo.y; a3.z += hi.x; a3.w += hi.y;
        }
    }
    for (; i < end; i++) {
        int r0 = g_srow[i];
        uint2 u0 = reinterpret_cast<const uint2*>(g_xh + ((size_t)r0 << 6))[hw];
        float2 lo = __half22float2(*reinterpret_cast<__half2*>(&u0.x));
        float2 hi = __half22float2(*reinterpret_cast<__half2*>(&u0.y));
        a0.x += lo.x; a0.y += lo.y; a0.z += hi.x; a0.w += hi.y;
    }

    int deg = end - start;
    float inv = 1.0f / (float)(deg > 0 ? deg : 1);
    float4 o;
    o.x = (a0.x + a1.x + a2.x + a3.x) * inv;
    o.y = (a0.y + a1.y + a2.y + a3.y) * inv;
    o.z = (a0.z + a1.z + a2.z + a3.z) * inv;
    o.w = (a0.w + a1.w + a2.w + a3.w) * inv;
    *reinterpret_cast<float4*>(out + ((size_t)node << 6) + (hw << 2)) = o;
}

extern "C" void kernel_launch(void* const* d_in, const int* in_sizes, int n_in,
                              void* d_out, int out_size) {
    const float* x    = (const float*)d_in[0];
    const int*   edge = (const int*)d_in[1];
    float*       out  = (float*)d_out;

    const int n   = in_sizes[0] / 64;   // 50000
    const int E   = in_sizes[1] / 2;    // 800000
    const int E4  = E / 4;              // 200000 (E % 4 == 0)
    const int n16 = n * 16;             // float4 count of x = 800000
    const int* row = edge;              // edge_index[0, :]
    const int* col = edge + E;          // edge_index[1, :]

    const int nb_scan    = (n + SCAN_BLK - 1) / SCAN_BLK;   // 49
    const int cvtBlocks  = (n16 + 255) / 256;               // 3125
    const int histBlocks = (E4 + 255) / 256;                // 782

    k_prep   <<<cvtBlocks + histBlocks, 256>>>(x, col, n16, E4, cvtBlocks);
    k_scan   <<<nb_scan, SCAN_BLK>>>(n, nb_scan);
    k_scatter<<<histBlocks, 256>>>(row, col, E4);
    // half-warp per node: 16 groups / 256-thread block
    k_gather <<<(n + 15) / 16, 256>>>(out, n);
}